// round 14
// baseline (speedup 1.0000x reference)
#include <cuda_runtime.h>
#include <cuda_bf16.h>
#include <cstdint>
#include <cstddef>

#define BnW   2048
#define NW    144
#define DIM   256
#define NH    8
#define HD    32
#define NTOK  (BnW * NW)            /* 294912 */
#define QKVN  (3 * DIM)             /* 768 */
#define KSTORE 512                  /* split-bf16 stored K: [hi|lo] */
#define SCALE 0.17677669529663687f

// ---------------- scratch (device globals: allocation-free rule) -------------
__device__ __nv_bfloat16 g_qkvh[(size_t)NTOK * QKVN];    // qkv hi plane
__device__ __nv_bfloat16 g_qkvl[(size_t)NTOK * QKVN];    // qkv lo plane
__device__ __nv_bfloat16 g_ax[(size_t)NTOK * KSTORE];    // x ext [Ah|Al]
__device__ __nv_bfloat16 g_attx[(size_t)NTOK * KSTORE];  // attn out ext [Oh|Ol]
__device__ __nv_bfloat16 g_bq[(size_t)QKVN * KSTORE];    // qkv_w ext [Bh|Bl] (q scaled)
__device__ __nv_bfloat16 g_bp[(size_t)DIM * KSTORE];     // proj_w ext
__device__ float         g_sbias[QKVN];                  // scaled qkv bias
__device__ float         g_bias[NH * NW * NW];           // [h][n][m] RPB

// ======================= baseline-PTX tensor-core helpers ====================
__device__ __forceinline__ uint32_t smem_u32(const void* p) {
    uint32_t a;
    asm("{ .reg .u64 t; cvta.to.shared.u64 t, %1; cvt.u32.u64 %0, t; }"
        : "=r"(a) : "l"(p));
    return a;
}
#define LDMX4(r0, r1, r2, r3, addr) \
    asm volatile("ldmatrix.sync.aligned.m8n8.x4.shared.b16 {%0,%1,%2,%3}, [%4];" \
                 : "=r"(r0), "=r"(r1), "=r"(r2), "=r"(r3) : "r"(addr))
#define LDMX4T(r0, r1, r2, r3, addr) \
    asm volatile("ldmatrix.sync.aligned.m8n8.x4.trans.shared.b16 {%0,%1,%2,%3}, [%4];" \
                 : "=r"(r0), "=r"(r1), "=r"(r2), "=r"(r3) : "r"(addr))
#define MMA16816(d, a, b0, b1) \
    asm volatile("mma.sync.aligned.m16n8k16.row.col.f32.bf16.bf16.f32 " \
                 "{%0,%1,%2,%3}, {%4,%5,%6,%7}, {%8,%9}, {%0,%1,%2,%3};" \
                 : "+f"((d)[0]), "+f"((d)[1]), "+f"((d)[2]), "+f"((d)[3]) \
                 : "r"((a)[0]), "r"((a)[1]), "r"((a)[2]), "r"((a)[3]), \
                   "r"(b0), "r"(b1))
#define CPASYNC16(s, g) \
    asm volatile("cp.async.cg.shared.global [%0], [%1], 16;" :: "r"(s), "l"(g))
#define CP_COMMIT() asm volatile("cp.async.commit_group;" ::: "memory")
#define CP_WAIT1()  asm volatile("cp.async.wait_group 1;" ::: "memory")
#define CP_WAIT0()  asm volatile("cp.async.wait_group 0;" ::: "memory")

// ======================= split-bf16 helpers ==================================
__device__ __forceinline__ void bf_split(float f, unsigned short& h, unsigned short& l) {
    __nv_bfloat16 hb = __float2bfloat16(f);
    __nv_bfloat16 lb = __float2bfloat16(f - __bfloat162float(hb));
    h = __bfloat16_as_ushort(hb);
    l = __bfloat16_as_ushort(lb);
}
__device__ __forceinline__ void split2(float x, float y, uint32_t& hp, uint32_t& lp) {
    unsigned short hx, lx, hy, ly;
    bf_split(x, hx, lx);
    bf_split(y, hy, ly);
    hp = (uint32_t)hx | ((uint32_t)hy << 16);
    lp = (uint32_t)lx | ((uint32_t)ly << 16);
}

// ======================= merged prep: conv_x + conv_w + biases ===============
// grid = 74836: [0,73728) conv_x | [73728,74752) conv_w | [74752,74833) rpb
//               [74833,74836) scaled qkv bias
__global__ __launch_bounds__(256) void prep_all_kernel(
    const float* __restrict__ x,
    const float* __restrict__ qkv_w, const float* __restrict__ proj_w,
    const float* __restrict__ rpb, const int* __restrict__ rel,
    const float* __restrict__ qkv_b) {
    int blk = blockIdx.x;
    if (blk < 73728) {
        size_t i = (size_t)blk * 256 + threadIdx.x;   // over NTOK*64
        size_t row = i >> 6;
        int c4 = (int)(i & 63) * 4;
        float4 v = *reinterpret_cast<const float4*>(x + row * DIM + c4);
        ushort4 hv, lv;
        bf_split(v.x, hv.x, lv.x); bf_split(v.y, hv.y, lv.y);
        bf_split(v.z, hv.z, lv.z); bf_split(v.w, hv.w, lv.w);
        __nv_bfloat16* base = g_ax + row * KSTORE;
        *reinterpret_cast<ushort4*>(base + c4)       = hv;
        *reinterpret_cast<ushort4*>(base + 256 + c4) = lv;
    } else if (blk < 74752) {
        int b2 = blk - 73728;
        const float* w;
        __nv_bfloat16* Bext;
        int N, nscale, i;
        if (b2 < 768) {
            w = qkv_w; Bext = g_bq; N = QKVN; nscale = DIM;
            i = b2 * 256 + threadIdx.x;
        } else {
            w = proj_w; Bext = g_bp; N = DIM; nscale = 0;
            i = (b2 - 768) * 256 + threadIdx.x;
        }
        int n = i >> 8, k = i & 255;
        float val = w[k * N + n];
        if (n < nscale) val *= SCALE;
        unsigned short h, l;
        bf_split(val, h, l);
        Bext[(size_t)n * KSTORE + k]       = __ushort_as_bfloat16(h);
        Bext[(size_t)n * KSTORE + 256 + k] = __ushort_as_bfloat16(l);
    } else if (blk < 74833) {
        int idx = (blk - 74752) * 256 + threadIdx.x;
        if (idx < NW * NW) {
            int r = rel[idx];
#pragma unroll
            for (int h = 0; h < NH; h++)
                g_bias[h * (NW * NW) + idx] = rpb[r * NH + h];
        }
    } else {
        int i = (blk - 74833) * 256 + threadIdx.x;
        if (i < QKVN) g_sbias[i] = qkv_b[i] * (i < DIM ? SCALE : 1.0f);
    }
}

// ======================= mma.sync GEMM (proven 128x128, 2-stage) =============
// PACK=true: write split planes (g_qkvh/g_qkvl). PACK=false: fp32 out.
#define SPITCH 80
#define STAGE_BYTES (128 * SPITCH)          /* 10240 per buffer */
#define SMEM_GEMM (8 * STAGE_BYTES)         /* 81920 */

template <bool PACK>
__global__ __launch_bounds__(256, 2) void gemm_mma_kernel(
    const __nv_bfloat16* __restrict__ Aext,
    const __nv_bfloat16* __restrict__ Bext,
    const float* __restrict__ bias,
    void* __restrict__ CoutH, void* __restrict__ CoutL, int Ntot) {
    extern __shared__ char gsm[];
    const uint32_t sAb = smem_u32(gsm);
    const uint32_t sBb = sAb + 4 * STAGE_BYTES;

    const int tid = threadIdx.x;
    const int w = tid >> 5, l = tid & 31;
    const int wm = w & 1, wn = w >> 1;
    const int tileN = blockIdx.x, tileM = blockIdx.y;

    const char* Ab = reinterpret_cast<const char*>(Aext) +
                     (size_t)tileM * 128 * (KSTORE * 2);
    const char* Bb = reinterpret_cast<const char*>(Bext) +
                     (size_t)tileN * 128 * (KSTORE * 2);

    const int lrow = tid >> 2;
    const int lseg = (tid & 3) * 16;

    float acc[4][4][4];
#pragma unroll
    for (int mf = 0; mf < 4; mf++)
#pragma unroll
        for (int nf = 0; nf < 4; nf++)
#pragma unroll
            for (int r = 0; r < 4; r++) acc[mf][nf][r] = 0.f;

#define ISSUE_GROUP(gg) do {                                                      \
        const int _g = (gg);                                                      \
        const uint32_t _sa = sAb + (uint32_t)(_g & 1) * (2 * STAGE_BYTES);        \
        const uint32_t _sb = sBb + (uint32_t)(_g & 1) * (2 * STAGE_BYTES);        \
        const size_t _r1 = (size_t)lrow * (KSTORE * 2);                           \
        const size_t _r2 = (size_t)(lrow + 64) * (KSTORE * 2);                    \
        const int _hc = _g * 64 + lseg;                                           \
        const int _lc = 512 + _g * 64 + lseg;                                     \
        CPASYNC16(_sa + lrow * SPITCH + lseg,              Ab + _r1 + _hc);       \
        CPASYNC16(_sa + (lrow + 64) * SPITCH + lseg,       Ab + _r2 + _hc);       \
        CPASYNC16(_sa + STAGE_BYTES + lrow * SPITCH + lseg,        Ab + _r1 + _lc); \
        CPASYNC16(_sa + STAGE_BYTES + (lrow + 64) * SPITCH + lseg, Ab + _r2 + _lc); \
        CPASYNC16(_sb + lrow * SPITCH + lseg,              Bb + _r1 + _hc);       \
        CPASYNC16(_sb + (lrow + 64) * SPITCH + lseg,       Bb + _r2 + _hc);       \
        CPASYNC16(_sb + STAGE_BYTES + lrow * SPITCH + lseg,        Bb + _r1 + _lc); \
        CPASYNC16(_sb + STAGE_BYTES + (lrow + 64) * SPITCH + lseg, Bb + _r2 + _lc); \
        CP_COMMIT();                                                              \
    } while (0)

    ISSUE_GROUP(0);
    ISSUE_GROUP(1);

    const uint32_t aRowOff = (uint32_t)(wm * 64 + (l & 15)) * SPITCH + (l >> 4) * 16;
    const uint32_t bRowOff = (uint32_t)(wn * 32 + ((l >> 4) * 8 + (l & 7))) * SPITCH +
                             ((l >> 3) & 1) * 16;

    for (int g = 0; g < 8; g++) {
        if (g < 7) CP_WAIT1(); else CP_WAIT0();
        __syncthreads();

        const uint32_t st = (uint32_t)(g & 1) * (2 * STAGE_BYTES);
        const uint32_t aH = sAb + st + aRowOff;
        const uint32_t aL = aH + STAGE_BYTES;
        const uint32_t bH = sBb + st + bRowOff;
        const uint32_t bL = bH + STAGE_BYTES;

#pragma unroll
        for (int ks = 0; ks < 2; ks++) {
            uint32_t ah[4][4], al[4][4], bf[2][4];
#pragma unroll
            for (int mf = 0; mf < 4; mf++)
                LDMX4(ah[mf][0], ah[mf][1], ah[mf][2], ah[mf][3],
                      aH + mf * (16 * SPITCH) + ks * 32);
#pragma unroll
            for (int n2 = 0; n2 < 2; n2++)
                LDMX4(bf[n2][0], bf[n2][1], bf[n2][2], bf[n2][3],
                      bH + n2 * (16 * SPITCH) + ks * 32);
#pragma unroll
            for (int mf = 0; mf < 4; mf++)
#pragma unroll
                for (int nf = 0; nf < 4; nf++)
                    MMA16816(acc[mf][nf], ah[mf],
                             bf[nf >> 1][(nf & 1) * 2],
                             bf[nf >> 1][(nf & 1) * 2 + 1]);
#pragma unroll
            for (int mf = 0; mf < 4; mf++)
                LDMX4(al[mf][0], al[mf][1], al[mf][2], al[mf][3],
                      aL + mf * (16 * SPITCH) + ks * 32);
#pragma unroll
            for (int mf = 0; mf < 4; mf++)
#pragma unroll
                for (int nf = 0; nf < 4; nf++)
                    MMA16816(acc[mf][nf], al[mf],
                             bf[nf >> 1][(nf & 1) * 2],
                             bf[nf >> 1][(nf & 1) * 2 + 1]);
#pragma unroll
            for (int n2 = 0; n2 < 2; n2++)
                LDMX4(bf[n2][0], bf[n2][1], bf[n2][2], bf[n2][3],
                      bL + n2 * (16 * SPITCH) + ks * 32);
#pragma unroll
            for (int mf = 0; mf < 4; mf++)
#pragma unroll
                for (int nf = 0; nf < 4; nf++)
                    MMA16816(acc[mf][nf], ah[mf],
                             bf[nf >> 1][(nf & 1) * 2],
                             bf[nf >> 1][(nf & 1) * 2 + 1]);
        }
        __syncthreads();
        if (g + 2 < 8) ISSUE_GROUP(g + 2);
    }
#undef ISSUE_GROUP

    const int rbase = tileM * 128 + wm * 64 + (l >> 2);
    const int cbase = tileN * 128 + wn * 32 + (l & 3) * 2;
#pragma unroll
    for (int mf = 0; mf < 4; mf++) {
#pragma unroll
        for (int nf = 0; nf < 4; nf++) {
            const int col = cbase + nf * 8;
            const float b0 = bias[col], b1 = bias[col + 1];
            const size_t r0 = (size_t)(rbase + mf * 16) * Ntot + col;
            const size_t r1 = r0 + (size_t)8 * Ntot;
            if (PACK) {
                uint32_t hp0, lp0, hp1, lp1;
                split2(acc[mf][nf][0] + b0, acc[mf][nf][1] + b1, hp0, lp0);
                split2(acc[mf][nf][2] + b0, acc[mf][nf][3] + b1, hp1, lp1);
                __nv_bfloat16* H = reinterpret_cast<__nv_bfloat16*>(CoutH);
                __nv_bfloat16* L = reinterpret_cast<__nv_bfloat16*>(CoutL);
                *reinterpret_cast<uint32_t*>(H + r0) = hp0;
                *reinterpret_cast<uint32_t*>(L + r0) = lp0;
                *reinterpret_cast<uint32_t*>(H + r1) = hp1;
                *reinterpret_cast<uint32_t*>(L + r1) = lp1;
            } else {
                float* C = reinterpret_cast<float*>(CoutH);
                *reinterpret_cast<float2*>(C + r0) =
                    make_float2(acc[mf][nf][0] + b0, acc[mf][nf][1] + b1);
                *reinterpret_cast<float2*>(C + r1) =
                    make_float2(acc[mf][nf][2] + b0, acc[mf][nf][3] + b1);
            }
        }
    }
}

// ======================= tensor-core attention v6 ============================
// staging is now pure cp.async 16B copies from the hi/lo planes.
#define QPITCH 144
#define KPITCH 144
#define VPITCH 144
#define OFF_Q   0
#define OFF_K   (144 * QPITCH)            /* 20736 */
#define OFF_V   (OFF_K + 144 * KPITCH)    /* 41472 */
#define SMEM_ATTN (OFF_V + 144 * VPITCH)  /* 62208 */

__global__ __launch_bounds__(288, 2) void attn_tc_kernel() {
    extern __shared__ char sm[];
    const uint32_t sb = smem_u32(sm);
    const int tid = threadIdx.x, l = tid & 31, w = tid >> 5;
    const int h = blockIdx.x, b = blockIdx.y;
    const size_t tokBase = (size_t)b * NW;

    // ---- stage Q, K, V via cp.async (12 per thread, no reg round trip) ----
    // idx -> (p = mtx*2+plane, r, s): 6 planes x 144 rows x 4 segs = 3456
#pragma unroll
    for (int it = 0; it < 12; it++) {
        int idx = it * 288 + tid;
        int p = idx / 576;
        int rem = idx - p * 576;
        int r = rem >> 2, s = rem & 3;
        int mtx = p >> 1, plane = p & 1;
        const __nv_bfloat16* plbase = plane ? g_qkvl : g_qkvh;
        const char* src = reinterpret_cast<const char*>(
            plbase + (tokBase + r) * QKVN + mtx * DIM + h * HD) + s * 16;
        uint32_t dst = sb + mtx * (144 * QPITCH) + r * QPITCH + plane * 64 + s * 16;
        CPASYNC16(dst, src);
    }
    CP_COMMIT();
    CP_WAIT0();
    __syncthreads();    // the only block barrier

    // ---- QK^T: S[16 x 144] per warp; grouped fragment reuse ----
    float accS[18][4];
#pragma unroll
    for (int j = 0; j < 18; j++)
#pragma unroll
        for (int e = 0; e < 4; e++) accS[j][e] = 0.f;

    const uint32_t aBase = sb + OFF_Q + (w * 16 + (l & 15)) * QPITCH + (l >> 4) * 16;
    const uint32_t bBase = sb + OFF_K +
        (((l >> 4) & 1) * 8 + (l & 7)) * KPITCH + ((l >> 3) & 1) * 16;
#pragma unroll
    for (int ks = 0; ks < 2; ks++) {
        uint32_t ah[4], al[4];
        LDMX4(ah[0], ah[1], ah[2], ah[3], aBase + ks * 32);
        LDMX4(al[0], al[1], al[2], al[3], aBase + 64 + ks * 32);
#pragma unroll
        for (int jp = 0; jp < 9; jp++) {
            uint32_t bf[4];
            LDMX4(bf[0], bf[1], bf[2], bf[3],
                  bBase + jp * (16 * KPITCH) + ks * 32);
            MMA16816(accS[jp * 2],     ah, bf[0], bf[1]);
            MMA16816(accS[jp * 2 + 1], ah, bf[2], bf[3]);
            MMA16816(accS[jp * 2],     al, bf[0], bf[1]);
            MMA16816(accS[jp * 2 + 1], al, bf[2], bf[3]);
            LDMX4(bf[0], bf[1], bf[2], bf[3],
                  bBase + jp * (16 * KPITCH) + 64 + ks * 32);
            MMA16816(accS[jp * 2],     ah, bf[0], bf[1]);
            MMA16816(accS[jp * 2 + 1], ah, bf[2], bf[3]);
        }
    }

    // ---- bias add + row max ----
    const float* bh = g_bias + h * (NW * NW);
    const int r0 = w * 16 + (l >> 2);
    float rmax0 = -1e30f, rmax1 = -1e30f;
#pragma unroll
    for (int j = 0; j < 18; j++) {
        const int c = j * 8 + (l & 3) * 2;
        float2 b0 = *reinterpret_cast<const float2*>(bh + r0 * NW + c);
        float2 b1 = *reinterpret_cast<const float2*>(bh + (r0 + 8) * NW + c);
        accS[j][0] += b0.x; accS[j][1] += b0.y;
        accS[j][2] += b1.x; accS[j][3] += b1.y;
        rmax0 = fmaxf(rmax0, fmaxf(accS[j][0], accS[j][1]));
        rmax1 = fmaxf(rmax1, fmaxf(accS[j][2], accS[j][3]));
    }
#pragma unroll
    for (int o = 1; o <= 2; o <<= 1) {
        rmax0 = fmaxf(rmax0, __shfl_xor_sync(0xffffffff, rmax0, o));
        rmax1 = fmaxf(rmax1, __shfl_xor_sync(0xffffffff, rmax1, o));
    }

    // ---- exp + row sum ----
    float rsum0 = 0.f, rsum1 = 0.f;
#pragma unroll
    for (int j = 0; j < 18; j++) {
        accS[j][0] = __expf(accS[j][0] - rmax0);
        accS[j][1] = __expf(accS[j][1] - rmax0);
        accS[j][2] = __expf(accS[j][2] - rmax1);
        accS[j][3] = __expf(accS[j][3] - rmax1);
        rsum0 += accS[j][0] + accS[j][1];
        rsum1 += accS[j][2] + accS[j][3];
    }
#pragma unroll
    for (int o = 1; o <= 2; o <<= 1) {
        rsum0 += __shfl_xor_sync(0xffffffff, rsum0, o);
        rsum1 += __shfl_xor_sync(0xffffffff, rsum1, o);
    }
    const float inv0 = 1.0f / rsum0;
    const float inv1 = 1.0f / rsum1;

    // ---- PV: inline P conversion; V via ldmatrix.trans ----
    float accO[4][4];
#pragma unroll
    for (int j = 0; j < 4; j++)
#pragma unroll
        for (int e = 0; e < 4; e++) accO[j][e] = 0.f;

    const uint32_t vLane = sb + OFF_V + (l & 15) * VPITCH + (l >> 4) * 16;
#pragma unroll
    for (int kk = 0; kk < 9; kk++) {
        uint32_t ph[4], pl[4];
        {
            const int j0 = 2 * kk, j1 = 2 * kk + 1;
            split2(accS[j0][0] * inv0, accS[j0][1] * inv0, ph[0], pl[0]);
            split2(accS[j0][2] * inv1, accS[j0][3] * inv1, ph[1], pl[1]);
            split2(accS[j1][0] * inv0, accS[j1][1] * inv0, ph[2], pl[2]);
            split2(accS[j1][2] * inv1, accS[j1][3] * inv1, ph[3], pl[3]);
        }
        const uint32_t vk = vLane + kk * (16 * VPITCH);
#pragma unroll
        for (int jp = 0; jp < 2; jp++) {
            uint32_t vf[4];
            LDMX4T(vf[0], vf[1], vf[2], vf[3], vk + jp * 32);
            MMA16816(accO[2 * jp],     ph, vf[0], vf[1]);
            MMA16816(accO[2 * jp + 1], ph, vf[2], vf[3]);
            MMA16816(accO[2 * jp],     pl, vf[0], vf[1]);
            MMA16816(accO[2 * jp + 1], pl, vf[2], vf[3]);
            LDMX4T(vf[0], vf[1], vf[2], vf[3], vk + jp * 32 + 64);
            MMA16816(accO[2 * jp],     ph, vf[0], vf[1]);
            MMA16816(accO[2 * jp + 1], ph, vf[2], vf[3]);
        }
    }

    // ---- write O ext [Oh|Ol] ----
#pragma unroll
    for (int j = 0; j < 4; j++) {
        const int cc = j * 8 + (l & 3) * 2;
        uint32_t hp0, lp0, hp1, lp1;
        split2(accO[j][0], accO[j][1], hp0, lp0);
        split2(accO[j][2], accO[j][3], hp1, lp1);
        __nv_bfloat16* o0 = g_attx + (tokBase + r0) * KSTORE + h * HD + cc;
        __nv_bfloat16* o1 = g_attx + (tokBase + r0 + 8) * KSTORE + h * HD + cc;
        *reinterpret_cast<uint32_t*>(o0)       = hp0;
        *reinterpret_cast<uint32_t*>(o0 + 256) = lp0;
        *reinterpret_cast<uint32_t*>(o1)       = hp1;
        *reinterpret_cast<uint32_t*>(o1 + 256) = lp1;
    }
}

// ---------------- launch ------------------------------------------------------
extern "C" void kernel_launch(void* const* d_in, const int* in_sizes, int n_in,
                              void* d_out, int out_size) {
    const float* x      = (const float*)d_in[0];
    const float* qkv_w  = (const float*)d_in[1];
    const float* qkv_b  = (const float*)d_in[2];
    const float* proj_w = (const float*)d_in[3];
    const float* proj_b = (const float*)d_in[4];
    const float* rpb    = (const float*)d_in[5];
    const int*   rel    = (const int*)d_in[6];

    __nv_bfloat16 *qh = nullptr, *ql = nullptr;
    __nv_bfloat16 *axp = nullptr, *attxp = nullptr, *bqp = nullptr, *bpp = nullptr;
    float* sbp = nullptr;
    cudaGetSymbolAddress((void**)&qh,    g_qkvh);
    cudaGetSymbolAddress((void**)&ql,    g_qkvl);
    cudaGetSymbolAddress((void**)&axp,   g_ax);
    cudaGetSymbolAddress((void**)&attxp, g_attx);
    cudaGetSymbolAddress((void**)&bqp,   g_bq);
    cudaGetSymbolAddress((void**)&bpp,   g_bp);
    cudaGetSymbolAddress((void**)&sbp,   g_sbias);

    static bool attr_done = false;
    if (!attr_done) {
        cudaFuncSetAttribute(attn_tc_kernel,
                             cudaFuncAttributeMaxDynamicSharedMemorySize, SMEM_ATTN);
        cudaFuncSetAttribute(gemm_mma_kernel<true>,
                             cudaFuncAttributeMaxDynamicSharedMemorySize, SMEM_GEMM);
        cudaFuncSetAttribute(gemm_mma_kernel<false>,
                             cudaFuncAttributeMaxDynamicSharedMemorySize, SMEM_GEMM);
        attr_done = true;
    }

    // launches: 0 prep, 1 QKV GEMM, 2 attention, 3 proj GEMM (profiled slot 3)
    prep_all_kernel<<<74836, 256>>>(x, qkv_w, proj_w, rpb, rel, qkv_b);
    gemm_mma_kernel<true><<<dim3(QKVN / 128, NTOK / 128), 256, SMEM_GEMM>>>(
        axp, bqp, sbp, qh, ql, QKVN);
    attn_tc_kernel<<<dim3(NH, BnW), 288, SMEM_ATTN>>>();
    gemm_mma_kernel<false><<<dim3(DIM / 128, NTOK / 128), 256, SMEM_GEMM>>>(
        attxp, bpp, proj_b, d_out, nullptr, DIM);
}

// round 15
// speedup vs baseline: 1.0676x; 1.0676x over previous
#include <cuda_runtime.h>
#include <cuda_bf16.h>
#include <cstdint>
#include <cstddef>

#define BnW   2048
#define NW    144
#define DIM   256
#define NH    8
#define HD    32
#define NTOK  (BnW * NW)            /* 294912 */
#define QKVN  (3 * DIM)             /* 768 */
#define KSTORE 512                  /* split-bf16 stored K: [hi|lo] */
#define SCALE 0.17677669529663687f

// ---------------- scratch (device globals: allocation-free rule) -------------
__device__ uint32_t      g_qkv[(size_t)NTOK * QKVN];     // packed (hi|lo) bf16 q|k|v
__device__ __nv_bfloat16 g_ax[(size_t)NTOK * KSTORE];    // x ext [Ah|Al]
__device__ __nv_bfloat16 g_attx[(size_t)NTOK * KSTORE];  // attn out ext [Oh|Ol]
__device__ __nv_bfloat16 g_bq[(size_t)QKVN * KSTORE];    // qkv_w ext [Bh|Bl] (q scaled)
__device__ __nv_bfloat16 g_bp[(size_t)DIM * KSTORE];     // proj_w ext
__device__ float         g_sbias[QKVN];                  // scaled qkv bias
__device__ float         g_bias[NH * NW * NW];           // [h][n][m] RPB

// ======================= baseline-PTX tensor-core helpers ====================
__device__ __forceinline__ uint32_t smem_u32(const void* p) {
    uint32_t a;
    asm("{ .reg .u64 t; cvta.to.shared.u64 t, %1; cvt.u32.u64 %0, t; }"
        : "=r"(a) : "l"(p));
    return a;
}
#define LDMX4(r0, r1, r2, r3, addr) \
    asm volatile("ldmatrix.sync.aligned.m8n8.x4.shared.b16 {%0,%1,%2,%3}, [%4];" \
                 : "=r"(r0), "=r"(r1), "=r"(r2), "=r"(r3) : "r"(addr))
#define LDMX4T(r0, r1, r2, r3, addr) \
    asm volatile("ldmatrix.sync.aligned.m8n8.x4.trans.shared.b16 {%0,%1,%2,%3}, [%4];" \
                 : "=r"(r0), "=r"(r1), "=r"(r2), "=r"(r3) : "r"(addr))
#define MMA16816(d, a, b0, b1) \
    asm volatile("mma.sync.aligned.m16n8k16.row.col.f32.bf16.bf16.f32 " \
                 "{%0,%1,%2,%3}, {%4,%5,%6,%7}, {%8,%9}, {%0,%1,%2,%3};" \
                 : "+f"((d)[0]), "+f"((d)[1]), "+f"((d)[2]), "+f"((d)[3]) \
                 : "r"((a)[0]), "r"((a)[1]), "r"((a)[2]), "r"((a)[3]), \
                   "r"(b0), "r"(b1))
#define CPASYNC16(s, g) \
    asm volatile("cp.async.cg.shared.global [%0], [%1], 16;" :: "r"(s), "l"(g))
#define CP_COMMIT() asm volatile("cp.async.commit_group;" ::: "memory")
#define CP_WAIT1()  asm volatile("cp.async.wait_group 1;" ::: "memory")
#define CP_WAIT0()  asm volatile("cp.async.wait_group 0;" ::: "memory")

// ======================= split-bf16 helpers ==================================
__device__ __forceinline__ void bf_split(float f, unsigned short& h, unsigned short& l) {
    __nv_bfloat16 hb = __float2bfloat16(f);
    __nv_bfloat16 lb = __float2bfloat16(f - __bfloat162float(hb));
    h = __bfloat16_as_ushort(hb);
    l = __bfloat16_as_ushort(lb);
}
__device__ __forceinline__ uint32_t pack_hl(float f) {
    unsigned short h, l;
    bf_split(f, h, l);
    return (uint32_t)h | ((uint32_t)l << 16);
}
__device__ __forceinline__ void split2(float x, float y, uint32_t& hp, uint32_t& lp) {
    unsigned short hx, lx, hy, ly;
    bf_split(x, hx, lx);
    bf_split(y, hy, ly);
    hp = (uint32_t)hx | ((uint32_t)hy << 16);
    lp = (uint32_t)lx | ((uint32_t)ly << 16);
}

// ======================= merged prep =========================================
// grid = 74836: [0,73728) conv_x | [73728,74752) conv_w | [74752,74833) rpb
//               [74833,74836) scaled qkv bias
__global__ __launch_bounds__(256) void prep_all_kernel(
    const float* __restrict__ x,
    const float* __restrict__ qkv_w, const float* __restrict__ proj_w,
    const float* __restrict__ rpb, const int* __restrict__ rel,
    const float* __restrict__ qkv_b) {
    int blk = blockIdx.x;
    if (blk < 73728) {
        size_t i = (size_t)blk * 256 + threadIdx.x;   // over NTOK*64
        size_t row = i >> 6;
        int c4 = (int)(i & 63) * 4;
        float4 v = *reinterpret_cast<const float4*>(x + row * DIM + c4);
        ushort4 hv, lv;
        bf_split(v.x, hv.x, lv.x); bf_split(v.y, hv.y, lv.y);
        bf_split(v.z, hv.z, lv.z); bf_split(v.w, hv.w, lv.w);
        __nv_bfloat16* base = g_ax + row * KSTORE;
        *reinterpret_cast<ushort4*>(base + c4)       = hv;
        *reinterpret_cast<ushort4*>(base + 256 + c4) = lv;
    } else if (blk < 74752) {
        int b2 = blk - 73728;
        const float* w;
        __nv_bfloat16* Bext;
        int N, nscale, i;
        if (b2 < 768) {
            w = qkv_w; Bext = g_bq; N = QKVN; nscale = DIM;
            i = b2 * 256 + threadIdx.x;
        } else {
            w = proj_w; Bext = g_bp; N = DIM; nscale = 0;
            i = (b2 - 768) * 256 + threadIdx.x;
        }
        int n = i >> 8, k = i & 255;
        float val = w[k * N + n];
        if (n < nscale) val *= SCALE;
        unsigned short h, l;
        bf_split(val, h, l);
        Bext[(size_t)n * KSTORE + k]       = __ushort_as_bfloat16(h);
        Bext[(size_t)n * KSTORE + 256 + k] = __ushort_as_bfloat16(l);
    } else if (blk < 74833) {
        int idx = (blk - 74752) * 256 + threadIdx.x;
        if (idx < NW * NW) {
            int r = rel[idx];
#pragma unroll
            for (int h = 0; h < NH; h++)
                g_bias[h * (NW * NW) + idx] = rpb[r * NH + h];
        }
    } else {
        int i = (blk - 74833) * 256 + threadIdx.x;
        if (i < QKVN) g_sbias[i] = qkv_b[i] * (i < DIM ? SCALE : 1.0f);
    }
}

// ======================= mma.sync GEMM (proven 128x128, 2-stage) =============
#define SPITCH 80
#define STAGE_BYTES (128 * SPITCH)          /* 10240 per buffer */
#define SMEM_GEMM (8 * STAGE_BYTES)         /* 81920 */

template <bool PACK>
__global__ __launch_bounds__(256, 2) void gemm_mma_kernel(
    const __nv_bfloat16* __restrict__ Aext,
    const __nv_bfloat16* __restrict__ Bext,
    const float* __restrict__ bias,
    void* __restrict__ Cout, int Ntot) {
    extern __shared__ char gsm[];
    const uint32_t sAb = smem_u32(gsm);
    const uint32_t sBb = sAb + 4 * STAGE_BYTES;

    const int tid = threadIdx.x;
    const int w = tid >> 5, l = tid & 31;
    const int wm = w & 1, wn = w >> 1;
    const int tileN = blockIdx.x, tileM = blockIdx.y;

    const char* Ab = reinterpret_cast<const char*>(Aext) +
                     (size_t)tileM * 128 * (KSTORE * 2);
    const char* Bb = reinterpret_cast<const char*>(Bext) +
                     (size_t)tileN * 128 * (KSTORE * 2);

    const int lrow = tid >> 2;
    const int lseg = (tid & 3) * 16;

    float acc[4][4][4];
#pragma unroll
    for (int mf = 0; mf < 4; mf++)
#pragma unroll
        for (int nf = 0; nf < 4; nf++)
#pragma unroll
            for (int r = 0; r < 4; r++) acc[mf][nf][r] = 0.f;

#define ISSUE_GROUP(gg) do {                                                      \
        const int _g = (gg);                                                      \
        const uint32_t _sa = sAb + (uint32_t)(_g & 1) * (2 * STAGE_BYTES);        \
        const uint32_t _sb = sBb + (uint32_t)(_g & 1) * (2 * STAGE_BYTES);        \
        const size_t _r1 = (size_t)lrow * (KSTORE * 2);                           \
        const size_t _r2 = (size_t)(lrow + 64) * (KSTORE * 2);                    \
        const int _hc = _g * 64 + lseg;                                           \
        const int _lc = 512 + _g * 64 + lseg;                                     \
        CPASYNC16(_sa + lrow * SPITCH + lseg,              Ab + _r1 + _hc);       \
        CPASYNC16(_sa + (lrow + 64) * SPITCH + lseg,       Ab + _r2 + _hc);       \
        CPASYNC16(_sa + STAGE_BYTES + lrow * SPITCH + lseg,        Ab + _r1 + _lc); \
        CPASYNC16(_sa + STAGE_BYTES + (lrow + 64) * SPITCH + lseg, Ab + _r2 + _lc); \
        CPASYNC16(_sb + lrow * SPITCH + lseg,              Bb + _r1 + _hc);       \
        CPASYNC16(_sb + (lrow + 64) * SPITCH + lseg,       Bb + _r2 + _hc);       \
        CPASYNC16(_sb + STAGE_BYTES + lrow * SPITCH + lseg,        Bb + _r1 + _lc); \
        CPASYNC16(_sb + STAGE_BYTES + (lrow + 64) * SPITCH + lseg, Bb + _r2 + _lc); \
        CP_COMMIT();                                                              \
    } while (0)

    ISSUE_GROUP(0);
    ISSUE_GROUP(1);

    const uint32_t aRowOff = (uint32_t)(wm * 64 + (l & 15)) * SPITCH + (l >> 4) * 16;
    const uint32_t bRowOff = (uint32_t)(wn * 32 + ((l >> 4) * 8 + (l & 7))) * SPITCH +
                             ((l >> 3) & 1) * 16;

    for (int g = 0; g < 8; g++) {
        if (g < 7) CP_WAIT1(); else CP_WAIT0();
        __syncthreads();

        const uint32_t st = (uint32_t)(g & 1) * (2 * STAGE_BYTES);
        const uint32_t aH = sAb + st + aRowOff;
        const uint32_t aL = aH + STAGE_BYTES;
        const uint32_t bH = sBb + st + bRowOff;
        const uint32_t bL = bH + STAGE_BYTES;

#pragma unroll
        for (int ks = 0; ks < 2; ks++) {
            uint32_t ah[4][4], al[4][4], bf[2][4];
#pragma unroll
            for (int mf = 0; mf < 4; mf++)
                LDMX4(ah[mf][0], ah[mf][1], ah[mf][2], ah[mf][3],
                      aH + mf * (16 * SPITCH) + ks * 32);
#pragma unroll
            for (int n2 = 0; n2 < 2; n2++)
                LDMX4(bf[n2][0], bf[n2][1], bf[n2][2], bf[n2][3],
                      bH + n2 * (16 * SPITCH) + ks * 32);
#pragma unroll
            for (int mf = 0; mf < 4; mf++)
#pragma unroll
                for (int nf = 0; nf < 4; nf++)
                    MMA16816(acc[mf][nf], ah[mf],
                             bf[nf >> 1][(nf & 1) * 2],
                             bf[nf >> 1][(nf & 1) * 2 + 1]);
#pragma unroll
            for (int mf = 0; mf < 4; mf++)
                LDMX4(al[mf][0], al[mf][1], al[mf][2], al[mf][3],
                      aL + mf * (16 * SPITCH) + ks * 32);
#pragma unroll
            for (int mf = 0; mf < 4; mf++)
#pragma unroll
                for (int nf = 0; nf < 4; nf++)
                    MMA16816(acc[mf][nf], al[mf],
                             bf[nf >> 1][(nf & 1) * 2],
                             bf[nf >> 1][(nf & 1) * 2 + 1]);
#pragma unroll
            for (int n2 = 0; n2 < 2; n2++)
                LDMX4(bf[n2][0], bf[n2][1], bf[n2][2], bf[n2][3],
                      bL + n2 * (16 * SPITCH) + ks * 32);
#pragma unroll
            for (int mf = 0; mf < 4; mf++)
#pragma unroll
                for (int nf = 0; nf < 4; nf++)
                    MMA16816(acc[mf][nf], ah[mf],
                             bf[nf >> 1][(nf & 1) * 2],
                             bf[nf >> 1][(nf & 1) * 2 + 1]);
        }
        __syncthreads();
        if (g + 2 < 8) ISSUE_GROUP(g + 2);
    }
#undef ISSUE_GROUP

    const int rbase = tileM * 128 + wm * 64 + (l >> 2);
    const int cbase = tileN * 128 + wn * 32 + (l & 3) * 2;
#pragma unroll
    for (int mf = 0; mf < 4; mf++) {
#pragma unroll
        for (int nf = 0; nf < 4; nf++) {
            const int col = cbase + nf * 8;
            const float b0 = bias[col], b1 = bias[col + 1];
            const size_t r0 = (size_t)(rbase + mf * 16) * Ntot + col;
            const size_t r1 = r0 + (size_t)8 * Ntot;
            if (PACK) {
                uint32_t* C = reinterpret_cast<uint32_t*>(Cout);
                *reinterpret_cast<uint2*>(C + r0) =
                    make_uint2(pack_hl(acc[mf][nf][0] + b0), pack_hl(acc[mf][nf][1] + b1));
                *reinterpret_cast<uint2*>(C + r1) =
                    make_uint2(pack_hl(acc[mf][nf][2] + b0), pack_hl(acc[mf][nf][3] + b1));
            } else {
                float* C = reinterpret_cast<float*>(Cout);
                *reinterpret_cast<float2*>(C + r0) =
                    make_float2(acc[mf][nf][0] + b0, acc[mf][nf][1] + b1);
                *reinterpret_cast<float2*>(C + r1) =
                    make_float2(acc[mf][nf][2] + b0, acc[mf][nf][3] + b1);
            }
        }
    }
}

// ======================= tensor-core attention (round-10 + deferred norm) ====
#define QPITCH 144
#define KPITCH 144
#define VPITCH 144
#define OFF_Q   0
#define OFF_K   (144 * QPITCH)            /* 20736 */
#define OFF_V   (OFF_K + 144 * KPITCH)    /* 41472 */
#define SMEM_ATTN (OFF_V + 144 * VPITCH)  /* 62208 */

__global__ __launch_bounds__(288, 2) void attn_tc_kernel() {
    extern __shared__ char sm[];
    const uint32_t sb = smem_u32(sm);
    const int tid = threadIdx.x, l = tid & 31, w = tid >> 5;
    const int h = blockIdx.x, b = blockIdx.y;
    const size_t tokBase = (size_t)b * NW;

    // ---- stage Q, K, V (row-major hi|lo, wide 8B stores) ----
    for (int idx = tid; idx < 144 * 8; idx += 288) {
        int r = idx >> 3, d4 = (idx & 7) * 4;
        const uint32_t* src = g_qkv + (tokBase + r) * QKVN + h * HD + d4;
        char* dst = sm + r * QPITCH + d4 * 2;
#pragma unroll
        for (int mtx = 0; mtx < 3; mtx++) {
            uint4 e = *reinterpret_cast<const uint4*>(src + mtx * DIM);
            char* p = dst + mtx * (144 * QPITCH);
            *reinterpret_cast<uint2*>(p) =
                make_uint2(__byte_perm(e.x, e.y, 0x5410), __byte_perm(e.z, e.w, 0x5410));
            *reinterpret_cast<uint2*>(p + 64) =
                make_uint2(__byte_perm(e.x, e.y, 0x7632), __byte_perm(e.z, e.w, 0x7632));
        }
    }
    __syncthreads();    // the only block barrier

    // ---- QK^T: S[16 x 144] per warp; grouped fragment reuse ----
    float accS[18][4];
#pragma unroll
    for (int j = 0; j < 18; j++)
#pragma unroll
        for (int e = 0; e < 4; e++) accS[j][e] = 0.f;

    const uint32_t aBase = sb + OFF_Q + (w * 16 + (l & 15)) * QPITCH + (l >> 4) * 16;
    const uint32_t bBase = sb + OFF_K +
        (((l >> 4) & 1) * 8 + (l & 7)) * KPITCH + ((l >> 3) & 1) * 16;
#pragma unroll
    for (int ks = 0; ks < 2; ks++) {
        uint32_t ah[4], al[4];
        LDMX4(ah[0], ah[1], ah[2], ah[3], aBase + ks * 32);
        LDMX4(al[0], al[1], al[2], al[3], aBase + 64 + ks * 32);
#pragma unroll
        for (int jp = 0; jp < 9; jp++) {
            uint32_t bf[4];
            LDMX4(bf[0], bf[1], bf[2], bf[3],
                  bBase + jp * (16 * KPITCH) + ks * 32);
            MMA16816(accS[jp * 2],     ah, bf[0], bf[1]);
            MMA16816(accS[jp * 2 + 1], ah, bf[2], bf[3]);
            MMA16816(accS[jp * 2],     al, bf[0], bf[1]);
            MMA16816(accS[jp * 2 + 1], al, bf[2], bf[3]);
            LDMX4(bf[0], bf[1], bf[2], bf[3],
                  bBase + jp * (16 * KPITCH) + 64 + ks * 32);
            MMA16816(accS[jp * 2],     ah, bf[0], bf[1]);
            MMA16816(accS[jp * 2 + 1], ah, bf[2], bf[3]);
        }
    }

    // ---- bias add + row max ----
    const float* bh = g_bias + h * (NW * NW);
    const int r0 = w * 16 + (l >> 2);
    float rmax0 = -1e30f, rmax1 = -1e30f;
#pragma unroll
    for (int j = 0; j < 18; j++) {
        const int c = j * 8 + (l & 3) * 2;
        float2 b0 = *reinterpret_cast<const float2*>(bh + r0 * NW + c);
        float2 b1 = *reinterpret_cast<const float2*>(bh + (r0 + 8) * NW + c);
        accS[j][0] += b0.x; accS[j][1] += b0.y;
        accS[j][2] += b1.x; accS[j][3] += b1.y;
        rmax0 = fmaxf(rmax0, fmaxf(accS[j][0], accS[j][1]));
        rmax1 = fmaxf(rmax1, fmaxf(accS[j][2], accS[j][3]));
    }
#pragma unroll
    for (int o = 1; o <= 2; o <<= 1) {
        rmax0 = fmaxf(rmax0, __shfl_xor_sync(0xffffffff, rmax0, o));
        rmax1 = fmaxf(rmax1, __shfl_xor_sync(0xffffffff, rmax1, o));
    }

    // ---- exp + row sum ----
    float rsum0 = 0.f, rsum1 = 0.f;
#pragma unroll
    for (int j = 0; j < 18; j++) {
        accS[j][0] = __expf(accS[j][0] - rmax0);
        accS[j][1] = __expf(accS[j][1] - rmax0);
        accS[j][2] = __expf(accS[j][2] - rmax1);
        accS[j][3] = __expf(accS[j][3] - rmax1);
        rsum0 += accS[j][0] + accS[j][1];
        rsum1 += accS[j][2] + accS[j][3];
    }
#pragma unroll
    for (int o = 1; o <= 2; o <<= 1) {
        rsum0 += __shfl_xor_sync(0xffffffff, rsum0, o);
        rsum1 += __shfl_xor_sync(0xffffffff, rsum1, o);
    }
    const float inv0 = 1.0f / rsum0;
    const float inv1 = 1.0f / rsum1;

    // ---- PV with inline P conversion (UNNORMALIZED P; norm deferred to O) ----
    float accO[4][4];
#pragma unroll
    for (int j = 0; j < 4; j++)
#pragma unroll
        for (int e = 0; e < 4; e++) accO[j][e] = 0.f;

    const uint32_t vLane = sb + OFF_V + (l & 15) * VPITCH + (l >> 4) * 16;
#pragma unroll
    for (int kk = 0; kk < 9; kk++) {
        uint32_t ph[4], pl[4];
        {
            const int j0 = 2 * kk, j1 = 2 * kk + 1;
            split2(accS[j0][0], accS[j0][1], ph[0], pl[0]);
            split2(accS[j0][2], accS[j0][3], ph[1], pl[1]);
            split2(accS[j1][0], accS[j1][1], ph[2], pl[2]);
            split2(accS[j1][2], accS[j1][3], ph[3], pl[3]);
        }
        const uint32_t vk = vLane + kk * (16 * VPITCH);
#pragma unroll
        for (int jp = 0; jp < 2; jp++) {
            uint32_t vf[4];
            LDMX4T(vf[0], vf[1], vf[2], vf[3], vk + jp * 32);
            MMA16816(accO[2 * jp],     ph, vf[0], vf[1]);
            MMA16816(accO[2 * jp + 1], ph, vf[2], vf[3]);
            MMA16816(accO[2 * jp],     pl, vf[0], vf[1]);
            MMA16816(accO[2 * jp + 1], pl, vf[2], vf[3]);
            LDMX4T(vf[0], vf[1], vf[2], vf[3], vk + jp * 32 + 64);
            MMA16816(accO[2 * jp],     ph, vf[0], vf[1]);
            MMA16816(accO[2 * jp + 1], ph, vf[2], vf[3]);
        }
    }

    // ---- normalize + write O ext [Oh|Ol] ----
#pragma unroll
    for (int j = 0; j < 4; j++) {
        const int cc = j * 8 + (l & 3) * 2;
        uint32_t hp0, lp0, hp1, lp1;
        split2(accO[j][0] * inv0, accO[j][1] * inv0, hp0, lp0);
        split2(accO[j][2] * inv1, accO[j][3] * inv1, hp1, lp1);
        __nv_bfloat16* o0 = g_attx + (tokBase + r0) * KSTORE + h * HD + cc;
        __nv_bfloat16* o1 = g_attx + (tokBase + r0 + 8) * KSTORE + h * HD + cc;
        *reinterpret_cast<uint32_t*>(o0)       = hp0;
        *reinterpret_cast<uint32_t*>(o0 + 256) = lp0;
        *reinterpret_cast<uint32_t*>(o1)       = hp1;
        *reinterpret_cast<uint32_t*>(o1 + 256) = lp1;
    }
}

// ---------------- launch ------------------------------------------------------
extern "C" void kernel_launch(void* const* d_in, const int* in_sizes, int n_in,
                              void* d_out, int out_size) {
    const float* x      = (const float*)d_in[0];
    const float* qkv_w  = (const float*)d_in[1];
    const float* qkv_b  = (const float*)d_in[2];
    const float* proj_w = (const float*)d_in[3];
    const float* proj_b = (const float*)d_in[4];
    const float* rpb    = (const float*)d_in[5];
    const int*   rel    = (const int*)d_in[6];

    uint32_t* qkvbuf = nullptr;
    __nv_bfloat16 *axp = nullptr, *attxp = nullptr, *bqp = nullptr, *bpp = nullptr;
    float* sbp = nullptr;
    cudaGetSymbolAddress((void**)&qkvbuf, g_qkv);
    cudaGetSymbolAddress((void**)&axp,   g_ax);
    cudaGetSymbolAddress((void**)&attxp, g_attx);
    cudaGetSymbolAddress((void**)&bqp,   g_bq);
    cudaGetSymbolAddress((void**)&bpp,   g_bp);
    cudaGetSymbolAddress((void**)&sbp,   g_sbias);

    static bool attr_done = false;
    if (!attr_done) {
        cudaFuncSetAttribute(attn_tc_kernel,
                             cudaFuncAttributeMaxDynamicSharedMemorySize, SMEM_ATTN);
        cudaFuncSetAttribute(gemm_mma_kernel<true>,
                             cudaFuncAttributeMaxDynamicSharedMemorySize, SMEM_GEMM);
        cudaFuncSetAttribute(gemm_mma_kernel<false>,
                             cudaFuncAttributeMaxDynamicSharedMemorySize, SMEM_GEMM);
        attr_done = true;
    }

    // launches: 0 prep, 1 QKV GEMM, 2 attention, 3 proj GEMM
    prep_all_kernel<<<74836, 256>>>(x, qkv_w, proj_w, rpb, rel, qkv_b);
    gemm_mma_kernel<true><<<dim3(QKVN / 128, NTOK / 128), 256, SMEM_GEMM>>>(
        axp, bqp, sbp, qkvbuf, QKVN);
    attn_tc_kernel<<<dim3(NH, BnW), 288, SMEM_ATTN>>>();
    gemm_mma_kernel<false><<<dim3(DIM / 128, NTOK / 128), 256, SMEM_GEMM>>>(
        attxp, bpp, proj_b, d_out, DIM);
}

// round 16
// speedup vs baseline: 1.0681x; 1.0004x over previous
#include <cuda_runtime.h>
#include <cuda_bf16.h>
#include <cstdint>
#include <cstddef>

#define BnW   2048
#define NW    144
#define DIM   256
#define NH    8
#define HD    32
#define NTOK  (BnW * NW)            /* 294912 */
#define QKVN  (3 * DIM)             /* 768 */
#define KSTORE 512                  /* split-bf16 stored K: [hi|lo] */
#define SCALE 0.17677669529663687f

// ---------------- scratch (device globals: allocation-free rule) -------------
__device__ uint32_t      g_qkv[(size_t)NTOK * QKVN];     // packed (hi|lo) bf16 q|k|v
__device__ __nv_bfloat16 g_ax[(size_t)NTOK * KSTORE];    // x ext [Ah|Al]
__device__ __nv_bfloat16 g_attx[(size_t)NTOK * KSTORE];  // attn out ext [Oh|Ol]
__device__ __nv_bfloat16 g_bq[(size_t)QKVN * KSTORE];    // qkv_w ext [Bh|Bl] (q scaled)
__device__ __nv_bfloat16 g_bp[(size_t)DIM * KSTORE];     // proj_w ext
__device__ float         g_sbias[QKVN];                  // scaled qkv bias
__device__ float         g_bias[NH * NW * NW];           // [h][n][m] RPB

// ======================= baseline-PTX tensor-core helpers ====================
__device__ __forceinline__ uint32_t smem_u32(const void* p) {
    uint32_t a;
    asm("{ .reg .u64 t; cvta.to.shared.u64 t, %1; cvt.u32.u64 %0, t; }"
        : "=r"(a) : "l"(p));
    return a;
}
#define LDMX4(r0, r1, r2, r3, addr) \
    asm volatile("ldmatrix.sync.aligned.m8n8.x4.shared.b16 {%0,%1,%2,%3}, [%4];" \
                 : "=r"(r0), "=r"(r1), "=r"(r2), "=r"(r3) : "r"(addr))
#define LDMX4T(r0, r1, r2, r3, addr) \
    asm volatile("ldmatrix.sync.aligned.m8n8.x4.trans.shared.b16 {%0,%1,%2,%3}, [%4];" \
                 : "=r"(r0), "=r"(r1), "=r"(r2), "=r"(r3) : "r"(addr))
#define MMA16816(d, a, b0, b1) \
    asm volatile("mma.sync.aligned.m16n8k16.row.col.f32.bf16.bf16.f32 " \
                 "{%0,%1,%2,%3}, {%4,%5,%6,%7}, {%8,%9}, {%0,%1,%2,%3};" \
                 : "+f"((d)[0]), "+f"((d)[1]), "+f"((d)[2]), "+f"((d)[3]) \
                 : "r"((a)[0]), "r"((a)[1]), "r"((a)[2]), "r"((a)[3]), \
                   "r"(b0), "r"(b1))
#define CPASYNC16(s, g) \
    asm volatile("cp.async.cg.shared.global [%0], [%1], 16;" :: "r"(s), "l"(g))
#define CP_COMMIT() asm volatile("cp.async.commit_group;" ::: "memory")
#define CP_WAIT1()  asm volatile("cp.async.wait_group 1;" ::: "memory")
#define CP_WAIT0()  asm volatile("cp.async.wait_group 0;" ::: "memory")

// ======================= split-bf16 helpers ==================================
__device__ __forceinline__ void bf_split(float f, unsigned short& h, unsigned short& l) {
    __nv_bfloat16 hb = __float2bfloat16(f);
    __nv_bfloat16 lb = __float2bfloat16(f - __bfloat162float(hb));
    h = __bfloat16_as_ushort(hb);
    l = __bfloat16_as_ushort(lb);
}
__device__ __forceinline__ uint32_t pack_hl(float f) {
    unsigned short h, l;
    bf_split(f, h, l);
    return (uint32_t)h | ((uint32_t)l << 16);
}
__device__ __forceinline__ void split2(float x, float y, uint32_t& hp, uint32_t& lp) {
    unsigned short hx, lx, hy, ly;
    bf_split(x, hx, lx);
    bf_split(y, hy, ly);
    hp = (uint32_t)hx | ((uint32_t)hy << 16);
    lp = (uint32_t)lx | ((uint32_t)ly << 16);
}

// ======================= merged prep =========================================
__global__ __launch_bounds__(256) void prep_all_kernel(
    const float* __restrict__ x,
    const float* __restrict__ qkv_w, const float* __restrict__ proj_w,
    const float* __restrict__ rpb, const int* __restrict__ rel,
    const float* __restrict__ qkv_b) {
    int blk = blockIdx.x;
    if (blk < 73728) {
        size_t i = (size_t)blk * 256 + threadIdx.x;   // over NTOK*64
        size_t row = i >> 6;
        int c4 = (int)(i & 63) * 4;
        float4 v = *reinterpret_cast<const float4*>(x + row * DIM + c4);
        ushort4 hv, lv;
        bf_split(v.x, hv.x, lv.x); bf_split(v.y, hv.y, lv.y);
        bf_split(v.z, hv.z, lv.z); bf_split(v.w, hv.w, lv.w);
        __nv_bfloat16* base = g_ax + row * KSTORE;
        *reinterpret_cast<ushort4*>(base + c4)       = hv;
        *reinterpret_cast<ushort4*>(base + 256 + c4) = lv;
    } else if (blk < 74752) {
        int b2 = blk - 73728;
        const float* w;
        __nv_bfloat16* Bext;
        int N, nscale, i;
        if (b2 < 768) {
            w = qkv_w; Bext = g_bq; N = QKVN; nscale = DIM;
            i = b2 * 256 + threadIdx.x;
        } else {
            w = proj_w; Bext = g_bp; N = DIM; nscale = 0;
            i = (b2 - 768) * 256 + threadIdx.x;
        }
        int n = i >> 8, k = i & 255;
        float val = w[k * N + n];
        if (n < nscale) val *= SCALE;
        unsigned short h, l;
        bf_split(val, h, l);
        Bext[(size_t)n * KSTORE + k]       = __ushort_as_bfloat16(h);
        Bext[(size_t)n * KSTORE + 256 + k] = __ushort_as_bfloat16(l);
    } else if (blk < 74833) {
        int idx = (blk - 74752) * 256 + threadIdx.x;
        if (idx < NW * NW) {
            int r = rel[idx];
#pragma unroll
            for (int h = 0; h < NH; h++)
                g_bias[h * (NW * NW) + idx] = rpb[r * NH + h];
        }
    } else {
        int i = (blk - 74833) * 256 + threadIdx.x;
        if (i < QKVN) g_sbias[i] = qkv_b[i] * (i < DIM ? SCALE : 1.0f);
    }
}

// ======================= mma.sync GEMM (proven 128x128, 2-stage) =============
#define SPITCH 80
#define STAGE_BYTES (128 * SPITCH)          /* 10240 per buffer */
#define SMEM_GEMM (8 * STAGE_BYTES)         /* 81920 */

template <bool PACK>
__global__ __launch_bounds__(256, 2) void gemm_mma_kernel(
    const __nv_bfloat16* __restrict__ Aext,
    const __nv_bfloat16* __restrict__ Bext,
    const float* __restrict__ bias,
    void* __restrict__ Cout, int Ntot) {
    extern __shared__ char gsm[];
    const uint32_t sAb = smem_u32(gsm);
    const uint32_t sBb = sAb + 4 * STAGE_BYTES;

    const int tid = threadIdx.x;
    const int w = tid >> 5, l = tid & 31;
    const int wm = w & 1, wn = w >> 1;
    const int tileN = blockIdx.x, tileM = blockIdx.y;

    const char* Ab = reinterpret_cast<const char*>(Aext) +
                     (size_t)tileM * 128 * (KSTORE * 2);
    const char* Bb = reinterpret_cast<const char*>(Bext) +
                     (size_t)tileN * 128 * (KSTORE * 2);

    const int lrow = tid >> 2;
    const int lseg = (tid & 3) * 16;

    float acc[4][4][4];
#pragma unroll
    for (int mf = 0; mf < 4; mf++)
#pragma unroll
        for (int nf = 0; nf < 4; nf++)
#pragma unroll
            for (int r = 0; r < 4; r++) acc[mf][nf][r] = 0.f;

#define ISSUE_GROUP(gg) do {                                                      \
        const int _g = (gg);                                                      \
        const uint32_t _sa = sAb + (uint32_t)(_g & 1) * (2 * STAGE_BYTES);        \
        const uint32_t _sb = sBb + (uint32_t)(_g & 1) * (2 * STAGE_BYTES);        \
        const size_t _r1 = (size_t)lrow * (KSTORE * 2);                           \
        const size_t _r2 = (size_t)(lrow + 64) * (KSTORE * 2);                    \
        const int _hc = _g * 64 + lseg;                                           \
        const int _lc = 512 + _g * 64 + lseg;                                     \
        CPASYNC16(_sa + lrow * SPITCH + lseg,              Ab + _r1 + _hc);       \
        CPASYNC16(_sa + (lrow + 64) * SPITCH + lseg,       Ab + _r2 + _hc);       \
        CPASYNC16(_sa + STAGE_BYTES + lrow * SPITCH + lseg,        Ab + _r1 + _lc); \
        CPASYNC16(_sa + STAGE_BYTES + (lrow + 64) * SPITCH + lseg, Ab + _r2 + _lc); \
        CPASYNC16(_sb + lrow * SPITCH + lseg,              Bb + _r1 + _hc);       \
        CPASYNC16(_sb + (lrow + 64) * SPITCH + lseg,       Bb + _r2 + _hc);       \
        CPASYNC16(_sb + STAGE_BYTES + lrow * SPITCH + lseg,        Bb + _r1 + _lc); \
        CPASYNC16(_sb + STAGE_BYTES + (lrow + 64) * SPITCH + lseg, Bb + _r2 + _lc); \
        CP_COMMIT();                                                              \
    } while (0)

    ISSUE_GROUP(0);
    ISSUE_GROUP(1);

    const uint32_t aRowOff = (uint32_t)(wm * 64 + (l & 15)) * SPITCH + (l >> 4) * 16;
    const uint32_t bRowOff = (uint32_t)(wn * 32 + ((l >> 4) * 8 + (l & 7))) * SPITCH +
                             ((l >> 3) & 1) * 16;

    for (int g = 0; g < 8; g++) {
        if (g < 7) CP_WAIT1(); else CP_WAIT0();
        __syncthreads();

        const uint32_t st = (uint32_t)(g & 1) * (2 * STAGE_BYTES);
        const uint32_t aH = sAb + st + aRowOff;
        const uint32_t aL = aH + STAGE_BYTES;
        const uint32_t bH = sBb + st + bRowOff;
        const uint32_t bL = bH + STAGE_BYTES;

#pragma unroll
        for (int ks = 0; ks < 2; ks++) {
            uint32_t ah[4][4], al[4][4], bf[2][4];
#pragma unroll
            for (int mf = 0; mf < 4; mf++)
                LDMX4(ah[mf][0], ah[mf][1], ah[mf][2], ah[mf][3],
                      aH + mf * (16 * SPITCH) + ks * 32);
#pragma unroll
            for (int n2 = 0; n2 < 2; n2++)
                LDMX4(bf[n2][0], bf[n2][1], bf[n2][2], bf[n2][3],
                      bH + n2 * (16 * SPITCH) + ks * 32);
#pragma unroll
            for (int mf = 0; mf < 4; mf++)
#pragma unroll
                for (int nf = 0; nf < 4; nf++)
                    MMA16816(acc[mf][nf], ah[mf],
                             bf[nf >> 1][(nf & 1) * 2],
                             bf[nf >> 1][(nf & 1) * 2 + 1]);
#pragma unroll
            for (int mf = 0; mf < 4; mf++)
                LDMX4(al[mf][0], al[mf][1], al[mf][2], al[mf][3],
                      aL + mf * (16 * SPITCH) + ks * 32);
#pragma unroll
            for (int mf = 0; mf < 4; mf++)
#pragma unroll
                for (int nf = 0; nf < 4; nf++)
                    MMA16816(acc[mf][nf], al[mf],
                             bf[nf >> 1][(nf & 1) * 2],
                             bf[nf >> 1][(nf & 1) * 2 + 1]);
#pragma unroll
            for (int n2 = 0; n2 < 2; n2++)
                LDMX4(bf[n2][0], bf[n2][1], bf[n2][2], bf[n2][3],
                      bL + n2 * (16 * SPITCH) + ks * 32);
#pragma unroll
            for (int mf = 0; mf < 4; mf++)
#pragma unroll
                for (int nf = 0; nf < 4; nf++)
                    MMA16816(acc[mf][nf], ah[mf],
                             bf[nf >> 1][(nf & 1) * 2],
                             bf[nf >> 1][(nf & 1) * 2 + 1]);
        }
        __syncthreads();
        if (g + 2 < 8) ISSUE_GROUP(g + 2);
    }
#undef ISSUE_GROUP

    const int rbase = tileM * 128 + wm * 64 + (l >> 2);
    const int cbase = tileN * 128 + wn * 32 + (l & 3) * 2;
#pragma unroll
    for (int mf = 0; mf < 4; mf++) {
#pragma unroll
        for (int nf = 0; nf < 4; nf++) {
            const int col = cbase + nf * 8;
            const float b0 = bias[col], b1 = bias[col + 1];
            const size_t r0 = (size_t)(rbase + mf * 16) * Ntot + col;
            const size_t r1 = r0 + (size_t)8 * Ntot;
            if (PACK) {
                uint32_t* C = reinterpret_cast<uint32_t*>(Cout);
                *reinterpret_cast<uint2*>(C + r0) =
                    make_uint2(pack_hl(acc[mf][nf][0] + b0), pack_hl(acc[mf][nf][1] + b1));
                *reinterpret_cast<uint2*>(C + r1) =
                    make_uint2(pack_hl(acc[mf][nf][2] + b0), pack_hl(acc[mf][nf][3] + b1));
            } else {
                float* C = reinterpret_cast<float*>(Cout);
                *reinterpret_cast<float2*>(C + r0) =
                    make_float2(acc[mf][nf][0] + b0, acc[mf][nf][1] + b1);
                *reinterpret_cast<float2*>(C + r1) =
                    make_float2(acc[mf][nf][2] + b0, acc[mf][nf][3] + b1);
            }
        }
    }
}

// ======================= tensor-core attention (WAR-free LDSM streams) =======
#define QPITCH 144
#define KPITCH 144
#define VPITCH 144
#define OFF_Q   0
#define OFF_K   (144 * QPITCH)            /* 20736 */
#define OFF_V   (OFF_K + 144 * KPITCH)    /* 41472 */
#define SMEM_ATTN (OFF_V + 144 * VPITCH)  /* 62208 */

__global__ __launch_bounds__(288, 2) void attn_tc_kernel() {
    extern __shared__ char sm[];
    const uint32_t sb = smem_u32(sm);
    const int tid = threadIdx.x, l = tid & 31, w = tid >> 5;
    const int h = blockIdx.x, b = blockIdx.y;
    const size_t tokBase = (size_t)b * NW;

    // ---- stage Q, K, V (row-major hi|lo, wide 8B stores) ----
    for (int idx = tid; idx < 144 * 8; idx += 288) {
        int r = idx >> 3, d4 = (idx & 7) * 4;
        const uint32_t* src = g_qkv + (tokBase + r) * QKVN + h * HD + d4;
        char* dst = sm + r * QPITCH + d4 * 2;
#pragma unroll
        for (int mtx = 0; mtx < 3; mtx++) {
            uint4 e = *reinterpret_cast<const uint4*>(src + mtx * DIM);
            char* p = dst + mtx * (144 * QPITCH);
            *reinterpret_cast<uint2*>(p) =
                make_uint2(__byte_perm(e.x, e.y, 0x5410), __byte_perm(e.z, e.w, 0x5410));
            *reinterpret_cast<uint2*>(p + 64) =
                make_uint2(__byte_perm(e.x, e.y, 0x7632), __byte_perm(e.z, e.w, 0x7632));
        }
    }
    __syncthreads();    // the only block barrier

    // ---- QK^T: S[16 x 144] per warp; independent hi/lo LDSM streams ----
    float accS[18][4];
#pragma unroll
    for (int j = 0; j < 18; j++)
#pragma unroll
        for (int e = 0; e < 4; e++) accS[j][e] = 0.f;

    const uint32_t aBase = sb + OFF_Q + (w * 16 + (l & 15)) * QPITCH + (l >> 4) * 16;
    const uint32_t bBase = sb + OFF_K +
        (((l >> 4) & 1) * 8 + (l & 7)) * KPITCH + ((l >> 3) & 1) * 16;
#pragma unroll
    for (int ks = 0; ks < 2; ks++) {
        uint32_t ah[4], al[4];
        LDMX4(ah[0], ah[1], ah[2], ah[3], aBase + ks * 32);
        LDMX4(al[0], al[1], al[2], al[3], aBase + 64 + ks * 32);
#pragma unroll
        for (int jp = 0; jp < 9; jp++) {
            uint32_t bfh[4], bfl[4];
            LDMX4(bfh[0], bfh[1], bfh[2], bfh[3],
                  bBase + jp * (16 * KPITCH) + ks * 32);           // Kh
            LDMX4(bfl[0], bfl[1], bfl[2], bfl[3],
                  bBase + jp * (16 * KPITCH) + 64 + ks * 32);      // Kl
            MMA16816(accS[jp * 2],     ah, bfh[0], bfh[1]);
            MMA16816(accS[jp * 2 + 1], ah, bfh[2], bfh[3]);
            MMA16816(accS[jp * 2],     al, bfh[0], bfh[1]);
            MMA16816(accS[jp * 2 + 1], al, bfh[2], bfh[3]);
            MMA16816(accS[jp * 2],     ah, bfl[0], bfl[1]);
            MMA16816(accS[jp * 2 + 1], ah, bfl[2], bfl[3]);
        }
    }

    // ---- bias add + row max ----
    const float* bh = g_bias + h * (NW * NW);
    const int r0 = w * 16 + (l >> 2);
    float rmax0 = -1e30f, rmax1 = -1e30f;
#pragma unroll
    for (int j = 0; j < 18; j++) {
        const int c = j * 8 + (l & 3) * 2;
        float2 b0 = *reinterpret_cast<const float2*>(bh + r0 * NW + c);
        float2 b1 = *reinterpret_cast<const float2*>(bh + (r0 + 8) * NW + c);
        accS[j][0] += b0.x; accS[j][1] += b0.y;
        accS[j][2] += b1.x; accS[j][3] += b1.y;
        rmax0 = fmaxf(rmax0, fmaxf(accS[j][0], accS[j][1]));
        rmax1 = fmaxf(rmax1, fmaxf(accS[j][2], accS[j][3]));
    }
#pragma unroll
    for (int o = 1; o <= 2; o <<= 1) {
        rmax0 = fmaxf(rmax0, __shfl_xor_sync(0xffffffff, rmax0, o));
        rmax1 = fmaxf(rmax1, __shfl_xor_sync(0xffffffff, rmax1, o));
    }

    // ---- exp + row sum ----
    float rsum0 = 0.f, rsum1 = 0.f;
#pragma unroll
    for (int j = 0; j < 18; j++) {
        accS[j][0] = __expf(accS[j][0] - rmax0);
        accS[j][1] = __expf(accS[j][1] - rmax0);
        accS[j][2] = __expf(accS[j][2] - rmax1);
        accS[j][3] = __expf(accS[j][3] - rmax1);
        rsum0 += accS[j][0] + accS[j][1];
        rsum1 += accS[j][2] + accS[j][3];
    }
#pragma unroll
    for (int o = 1; o <= 2; o <<= 1) {
        rsum0 += __shfl_xor_sync(0xffffffff, rsum0, o);
        rsum1 += __shfl_xor_sync(0xffffffff, rsum1, o);
    }
    const float inv0 = 1.0f / rsum0;
    const float inv1 = 1.0f / rsum1;

    // ---- PV: inline P conversion (unnormalized); independent Vh/Vl streams ----
    float accO[4][4];
#pragma unroll
    for (int j = 0; j < 4; j++)
#pragma unroll
        for (int e = 0; e < 4; e++) accO[j][e] = 0.f;

    const uint32_t vLane = sb + OFF_V + (l & 15) * VPITCH + (l >> 4) * 16;
#pragma unroll
    for (int kk = 0; kk < 9; kk++) {
        uint32_t ph[4], pl[4];
        {
            const int j0 = 2 * kk, j1 = 2 * kk + 1;
            split2(accS[j0][0], accS[j0][1], ph[0], pl[0]);
            split2(accS[j0][2], accS[j0][3], ph[1], pl[1]);
            split2(accS[j1][0], accS[j1][1], ph[2], pl[2]);
            split2(accS[j1][2], accS[j1][3], ph[3], pl[3]);
        }
        const uint32_t vk = vLane + kk * (16 * VPITCH);
#pragma unroll
        for (int jp = 0; jp < 2; jp++) {
            uint32_t vfh[4], vfl[4];
            LDMX4T(vfh[0], vfh[1], vfh[2], vfh[3], vk + jp * 32);
            LDMX4T(vfl[0], vfl[1], vfl[2], vfl[3], vk + jp * 32 + 64);
            MMA16816(accO[2 * jp],     ph, vfh[0], vfh[1]);
            MMA16816(accO[2 * jp + 1], ph, vfh[2], vfh[3]);
            MMA16816(accO[2 * jp],     pl, vfh[0], vfh[1]);
            MMA16816(accO[2 * jp + 1], pl, vfh[2], vfh[3]);
            MMA16816(accO[2 * jp],     ph, vfl[0], vfl[1]);
            MMA16816(accO[2 * jp + 1], ph, vfl[2], vfl[3]);
        }
    }

    // ---- normalize + write O ext [Oh|Ol] ----
#pragma unroll
    for (int j = 0; j < 4; j++) {
        const int cc = j * 8 + (l & 3) * 2;
        uint32_t hp0, lp0, hp1, lp1;
        split2(accO[j][0] * inv0, accO[j][1] * inv0, hp0, lp0);
        split2(accO[j][2] * inv1, accO[j][3] * inv1, hp1, lp1);
        __nv_bfloat16* o0 = g_attx + (tokBase + r0) * KSTORE + h * HD + cc;
        __nv_bfloat16* o1 = g_attx + (tokBase + r0 + 8) * KSTORE + h * HD + cc;
        *reinterpret_cast<uint32_t*>(o0)       = hp0;
        *reinterpret_cast<uint32_t*>(o0 + 256) = lp0;
        *reinterpret_cast<uint32_t*>(o1)       = hp1;
        *reinterpret_cast<uint32_t*>(o1 + 256) = lp1;
    }
}

// ---------------- launch ------------------------------------------------------
extern "C" void kernel_launch(void* const* d_in, const int* in_sizes, int n_in,
                              void* d_out, int out_size) {
    const float* x      = (const float*)d_in[0];
    const float* qkv_w  = (const float*)d_in[1];
    const float* qkv_b  = (const float*)d_in[2];
    const float* proj_w = (const float*)d_in[3];
    const float* proj_b = (const float*)d_in[4];
    const float* rpb    = (const float*)d_in[5];
    const int*   rel    = (const int*)d_in[6];

    uint32_t* qkvbuf = nullptr;
    __nv_bfloat16 *axp = nullptr, *attxp = nullptr, *bqp = nullptr, *bpp = nullptr;
    float* sbp = nullptr;
    cudaGetSymbolAddress((void**)&qkvbuf, g_qkv);
    cudaGetSymbolAddress((void**)&axp,   g_ax);
    cudaGetSymbolAddress((void**)&attxp, g_attx);
    cudaGetSymbolAddress((void**)&bqp,   g_bq);
    cudaGetSymbolAddress((void**)&bpp,   g_bp);
    cudaGetSymbolAddress((void**)&sbp,   g_sbias);

    static bool attr_done = false;
    if (!attr_done) {
        cudaFuncSetAttribute(attn_tc_kernel,
                             cudaFuncAttributeMaxDynamicSharedMemorySize, SMEM_ATTN);
        cudaFuncSetAttribute(gemm_mma_kernel<true>,
                             cudaFuncAttributeMaxDynamicSharedMemorySize, SMEM_GEMM);
        cudaFuncSetAttribute(gemm_mma_kernel<false>,
                             cudaFuncAttributeMaxDynamicSharedMemorySize, SMEM_GEMM);
        attr_done = true;
    }

    // launches: 0 prep, 1 QKV GEMM, 2 attention, 3 proj GEMM
    prep_all_kernel<<<74836, 256>>>(x, qkv_w, proj_w, rpb, rel, qkv_b);
    gemm_mma_kernel<true><<<dim3(QKVN / 128, NTOK / 128), 256, SMEM_GEMM>>>(
        axp, bqp, sbp, qkvbuf, QKVN);
    attn_tc_kernel<<<dim3(NH, BnW), 288, SMEM_ATTN>>>();
    gemm_mma_kernel<false><<<dim3(DIM / 128, NTOK / 128), 256, SMEM_GEMM>>>(
        attxp, bpp, proj_b, d_out, DIM);
}